// round 16
// baseline (speedup 1.0000x reference)
#include <cuda_runtime.h>

#define BB   8
#define VV   1200
#define NGT  (BB*VV)
#define TN   32
#define SP   65
#define EMAX 76800
#define NBCAP 640
#define TS   192          /* enc tile rows for msg */
#define NTILE 7           /* ceil(1200/192) */
#define RW   3            /* dest nodes per warp in k_msg */
#define RB   24           /* dest nodes per block (8 warps * 3) */
#define TILE_F4 (TS*16)   /* float4 per full tile */

__device__ float g_enc[NGT*64];
__device__ float g_msg[2*NGT*64];
__device__ float g_pred[NGT];
__device__ float g_dualp[NGT];
__device__ int   g_cols[NGT*64];
__device__ int   g_nnz[NGT];
__device__ float g_rowss[NGT];
__device__ int   g_nbcols[2*NGT*NBCAP];
__device__ int   g_nbnnz[2*NGT];
__device__ float g_nbinv[2*NGT];
__device__ int   g_nbseg[2*NGT*8];
__device__ int   g_eu[BB*EMAX];
__device__ int   g_ev[BB*EMAX];
__device__ float g_ep[BB*EMAX];
__device__ int   g_ecnt[BB];
__device__ float g_dualedge[BB];
__device__ float g_flowcost[BB];
__device__ float g_comb[132];

__device__ __forceinline__ float ftanh(float x){ float e=__expf(2.f*x); return 1.f-2.f/(e+1.f); }
__device__ __forceinline__ float fsig (float x){ return 1.f/(1.f+__expf(-x)); }
/* HW tanh: 1 MUFU op, ~6e-4 abs err — attention score path only */
__device__ __forceinline__ float htanh(float x){
    float y; asm("tanh.approx.f32 %0,%1;":"=f"(y):"f"(x)); return y;
}

__device__ __forceinline__ unsigned smem_u32(const void* p){
    unsigned r;
    asm("{ .reg .u64 t; cvta.to.shared.u64 t, %1; cvt.u32.u64 %0, t; }":"=r"(r):"l"(p));
    return r;
}
__device__ __forceinline__ void cpa16(unsigned dst, const float* src){
    asm volatile("cp.async.cg.shared.global [%0],[%1],16;"::"r"(dst),"l"(src));
}
__device__ __forceinline__ void cpcommit(){ asm volatile("cp.async.commit_group;":::"memory"); }
__device__ __forceinline__ void cpwaitall(){ asm volatile("cp.async.wait_all;":::"memory"); }
__device__ __forceinline__ void prefW(unsigned sdst, const float* W, int t){
    #pragma unroll
    for(int i=0;i<8;i++) cpa16(sdst + (unsigned)(t + i*128)*16u, W + (t + i*128)*4);
    cpcommit();
}
/* variable-size tile prefetch (n4 float4 elements, 256 threads) */
__device__ __forceinline__ void prefTile(unsigned sdst, const float* src, int n4, int t){
    for(int i=t;i<n4;i+=256) cpa16(sdst + (unsigned)i*16u, src + (size_t)i*4);
    cpcommit();
}

/* ---- collapse decoder MLPs + zero accumulators ---- */
__global__ void k_comb(const float* __restrict__ w0,const float* __restrict__ b0,
                       const float* __restrict__ w1,const float* __restrict__ b1,
                       const float* __restrict__ dw0,const float* __restrict__ db0,
                       const float* __restrict__ dw1,const float* __restrict__ db1){
    int d=threadIdx.x;
    if(d<BB){ g_ecnt[d]=0; g_dualedge[d]=0.f; }
    float s=0.f, sd=0.f;
    for(int e=0;e<64;e++){ s+=w0[d*64+e]*w1[e]; sd+=dw0[d*64+e]*dw1[e]; }
    g_comb[d]=s; g_comb[66+d]=sd;
    if(d==0){
        float bb=b1[0], bd=db1[0];
        for(int e=0;e<64;e++){ bb+=b0[e]*w1[e]; bd+=db0[e]*dw1[e]; }
        g_comb[64]=bb; g_comb[65]=bd;
    }
}

/* ---- encoder: enc = tanh(tanh(x W0 + b0) W1 + b1), x=[emb16,feat8] ---- */
__global__ __launch_bounds__(128) void k_enc(
        const float* __restrict__ feat, const float* __restrict__ emb,
        const float* __restrict__ w0, const float* __restrict__ b0,
        const float* __restrict__ w1, const float* __restrict__ b1){
    __shared__ __align__(16) float sW0[24*64];
    __shared__ __align__(16) float sW1[64*64];
    __shared__ __align__(16) float sB[128];
    __shared__ __align__(16) float sX[TN*24];
    __shared__ __align__(16) float sH[TN*SP];
    int t=threadIdx.x;
    int base=blockIdx.x*TN;
    for(int i=t;i<384;i+=128)  ((float4*)sW0)[i]=((const float4*)w0)[i];
    for(int i=t;i<1024;i+=128) ((float4*)sW1)[i]=((const float4*)w1)[i];
    if(t<64){ sB[t]=b0[t]; sB[64+t]=b1[t]; }
    for(int i=t;i<TN*24;i+=128){
        int n=i/24, d=i%24, g=base+n;
        sX[i]=(d<16)? emb[g*16+d] : feat[g*8+(d-16)];
    }
    __syncthreads();
    const int eq=t&15, ng=t>>4, e0=eq*4, n0=ng*4;
    float acc[4][4];
    #pragma unroll
    for(int i=0;i<4;i++){ float4 bb=*(const float4*)&sB[e0];
        acc[i][0]=bb.x; acc[i][1]=bb.y; acc[i][2]=bb.z; acc[i][3]=bb.w; }
    for(int d=0;d<24;d++){
        float4 w=*(const float4*)&sW0[d*64+e0];
        #pragma unroll
        for(int i=0;i<4;i++){ float x=sX[(n0+i)*24+d];
            acc[i][0]=fmaf(x,w.x,acc[i][0]); acc[i][1]=fmaf(x,w.y,acc[i][1]);
            acc[i][2]=fmaf(x,w.z,acc[i][2]); acc[i][3]=fmaf(x,w.w,acc[i][3]); }
    }
    #pragma unroll
    for(int i=0;i<4;i++)
        #pragma unroll
        for(int j=0;j<4;j++) sH[(n0+i)*SP+e0+j]=ftanh(acc[i][j]);
    __syncthreads();
    #pragma unroll
    for(int i=0;i<4;i++){ float4 bb=*(const float4*)&sB[64+e0];
        acc[i][0]=bb.x; acc[i][1]=bb.y; acc[i][2]=bb.z; acc[i][3]=bb.w; }
    #pragma unroll 4
    for(int d=0;d<64;d++){
        float4 w=*(const float4*)&sW1[d*64+e0];
        #pragma unroll
        for(int i=0;i<4;i++){ float x=sH[(n0+i)*SP+d];
            acc[i][0]=fmaf(x,w.x,acc[i][0]); acc[i][1]=fmaf(x,w.y,acc[i][1]);
            acc[i][2]=fmaf(x,w.z,acc[i][2]); acc[i][3]=fmaf(x,w.w,acc[i][3]); }
    }
    #pragma unroll
    for(int i=0;i<4;i++){
        float4 o; o.x=ftanh(acc[i][0]); o.y=ftanh(acc[i][1]);
        o.z=ftanh(acc[i][2]); o.w=ftanh(acc[i][3]);
        *(float4*)&g_enc[(base+n0+i)*64+e0]=o;
    }
}

/* ---- ordered CSR compaction, warp per row, float4 loads + ballot prefix -- */
__device__ __forceinline__ void csr_row_f4(const float* __restrict__ row,
                                           int* __restrict__ outCols, int cap,
                                           int lane, int* outCnt){
    const float4* r4=(const float4*)row;
    unsigned lt=(1u<<lane)-1u;
    int cnt=0;
    for(int i0=0;i0<300;i0+=32){
        int i=i0+lane;
        float4 v = (i<300)? r4[i] : make_float4(0.f,0.f,0.f,0.f);
        int f0=(v.x!=0.f), f1=(v.y!=0.f), f2=(v.z!=0.f), f3=(v.w!=0.f);
        unsigned m0=__ballot_sync(0xffffffffu,f0);
        unsigned m1=__ballot_sync(0xffffffffu,f1);
        unsigned m2=__ballot_sync(0xffffffffu,f2);
        unsigned m3=__ballot_sync(0xffffffffu,f3);
        int base=cnt + __popc(m0&lt)+__popc(m1&lt)+__popc(m2&lt)+__popc(m3&lt);
        int col0=i*4;
        if(f0){ if(base<cap) outCols[base]=col0;   base++; }
        if(f1){ if(base<cap) outCols[base]=col0+1; base++; }
        if(f2){ if(base<cap) outCols[base]=col0+2; base++; }
        if(f3){ if(base<cap) outCols[base]=col0+3; base++; }
        cnt += __popc(m0)+__popc(m1)+__popc(m2)+__popc(m3);
    }
    *outCnt=cnt;
}

__global__ __launch_bounds__(256) void k_csr_adj(const float* __restrict__ adj){
    int wr=(blockIdx.x*blockDim.x+threadIdx.x)>>5;
    if(wr>=NGT) return;
    int lane=threadIdx.x&31;
    int cnt;
    csr_row_f4(adj+(size_t)wr*VV, &g_cols[wr*64], 64, lane, &cnt);
    if(lane==0) g_nnz[wr]=min(cnt,64);
}

__global__ __launch_bounds__(256) void k_csr_nb(const float* __restrict__ nb){
    int wr=(blockIdx.x*blockDim.x+threadIdx.x)>>5;
    if(wr>=2*NGT) return;
    int lane=threadIdx.x&31;
    int cnt;
    const int* cols=&g_nbcols[(size_t)wr*NBCAP];
    csr_row_f4(nb+(size_t)wr*VV, &g_nbcols[(size_t)wr*NBCAP], NBCAP, lane, &cnt);
    int nnzc=min(cnt,NBCAP);
    if(lane<8){
        int sg;
        if(lane==0) sg=0;
        else if(lane==7) sg=nnzc;
        else{
            int key=lane*TS, lo=0, hi=nnzc;
            while(lo<hi){ int m=(lo+hi)>>1; if(cols[m]<key) lo=m+1; else hi=m; }
            sg=lo;
        }
        g_nbseg[wr*8+lane]=sg;
    }
    if(lane==0){
        g_nbnnz[wr]=nnzc;
        g_nbinv[wr]=1.f/fmaxf((float)cnt,1.f);
    }
}

/* ---- both-hop msg: smem-tiled SpMM with cp.async DOUBLE-BUFFERED tiles ---- */
__global__ __launch_bounds__(256) void k_msg(){
    extern __shared__ __align__(16) float sT[];    /* 2 x TS*64 floats = 96 KB */
    int t=threadIdx.x, lane=t&31, w=t>>5;
    int b=blockIdx.y;
    int v0=blockIdx.x*RB + w*RW;
    unsigned sTb=smem_u32(sT);

    float2 acc[2][RW];
    #pragma unroll
    for(int hp=0;hp<2;hp++)
        #pragma unroll
        for(int s=0;s<RW;s++) acc[hp][s]=make_float2(0.f,0.f);

    /* prologue: tile 0 -> buf0 */
    prefTile(sTb, &g_enc[(size_t)(b*VV)*64], TILE_F4, t);

    for(int tile=0;tile<NTILE;tile++){
        int tLo=tile*TS;
        cpwaitall(); __syncthreads();
        /* prefetch next tile into the other buffer (overlaps with gather) */
        if(tile+1<NTILE){
            int nLo=(tile+1)*TS;
            int nts=min(TS,VV-nLo);
            prefTile(sTb + (unsigned)(((tile+1)&1)*TS*64*4),
                     &g_enc[(size_t)(b*VV+nLo)*64], nts*16, t);
        }
        const float* buf=sT + (tile&1)*TS*64;
        #pragma unroll
        for(int hp=0;hp<2;hp++){
            #pragma unroll
            for(int s=0;s<RW;s++){
                int r=hp*NGT + b*VV + v0+s;
                int lo=g_nbseg[r*8+tile];
                int hi=g_nbseg[r*8+tile+1];
                const int* cl=&g_nbcols[(size_t)r*NBCAP];
                float2 a=acc[hp][s];
                int j=lo;
                for(; j+3<hi; j+=4){
                    int c0=cl[j]-tLo, c1=cl[j+1]-tLo, c2=cl[j+2]-tLo, c3=cl[j+3]-tLo;
                    float2 e0=*(const float2*)&buf[c0*64+lane*2];
                    float2 e1=*(const float2*)&buf[c1*64+lane*2];
                    float2 e2=*(const float2*)&buf[c2*64+lane*2];
                    float2 e3=*(const float2*)&buf[c3*64+lane*2];
                    a.x+=e0.x+e1.x+e2.x+e3.x;
                    a.y+=e0.y+e1.y+e2.y+e3.y;
                }
                for(; j<hi; j++){
                    int c=cl[j]-tLo;
                    float2 e=*(const float2*)&buf[c*64+lane*2];
                    a.x+=e.x; a.y+=e.y;
                }
                acc[hp][s]=a;
            }
        }
        __syncthreads();
    }
    #pragma unroll
    for(int hp=0;hp<2;hp++)
        #pragma unroll
        for(int s=0;s<RW;s++){
            int r=hp*NGT + b*VV + v0+s;
            float inv=g_nbinv[r];
            float2 o; o.x=acc[hp][s].x*inv; o.y=acc[hp][s].y*inv;
            *(float2*)&g_msg[(size_t)r*64+lane*2]=o;
        }
}

/* ---- fused graph layer: agg -> hop attention -> GRU, cp.async W pipeline -- */
#define SMF (4*TN*SP + 2*4096 + 512 + 256 + 64 + 832)
#define SMB (SMF*4)

__global__ __launch_bounds__(128) void k_node(
        const float* __restrict__ agg_w, const float* __restrict__ agg_b,
        const float* __restrict__ att_w, const float* __restrict__ att_b,
        const float* __restrict__ att_v,
        const float* __restrict__ gwu, const float* __restrict__ gbu,
        const float* __restrict__ gwr, const float* __restrict__ gbr,
        const float* __restrict__ gwc, const float* __restrict__ gbc){
    extern __shared__ __align__(16) float sm[];
    float* sEnc=sm;
    float* sM0 =sEnc+TN*SP;
    float* sM1 =sM0 +TN*SP;
    float* sNxt=sM1 +TN*SP;
    float* sW  =sNxt+TN*SP;      /* 2 x 4096 */
    float* sRed=sW+8192;
    float* sSc =sRed+512;
    float* sCw =sSc+256;
    float* sB  =sCw+64;

    int t=threadIdx.x;
    int base=blockIdx.x*TN;
    const int eq=t&15, ng=t>>4, e0=eq*4, n0=ng*4;
    unsigned swb=smem_u32(sW);

    prefW(swb, agg_w, t);                              /* stage0 W -> buf0 */

    for(int i=t;i<TN*64;i+=128){
        int n=i>>6, e=i&63;
        sEnc[n*SP+e]=g_enc[(base+n)*64+e];
        sM0 [n*SP+e]=g_msg[(size_t)(base+n)*64+e];
        sM1 [n*SP+e]=g_msg[(size_t)(NGT+base+n)*64+e];
    }
    if(t<128) sB[t]=agg_b[t];
    for(int i=t;i<256;i+=128){ sB[128+i]=att_b[i]; sB[384+i]=att_v[i]; }
    if(t<64){ sB[640+t]=gbu[t]; sB[704+t]=gbr[t]; sB[768+t]=gbc[t]; }
    cpwaitall(); __syncthreads();

    float acc[4][4];

    /* agg0: msg0 @ agg_w[0], prefetch agg_w[1] */
    prefW(swb+16384u, agg_w+4096, t);
    #pragma unroll
    for(int i=0;i<4;i++){ float4 bb=*(const float4*)&sB[e0];
        acc[i][0]=bb.x; acc[i][1]=bb.y; acc[i][2]=bb.z; acc[i][3]=bb.w; }
    #pragma unroll 4
    for(int d=0;d<64;d++){
        float4 w=*(const float4*)&sW[d*64+e0];
        #pragma unroll
        for(int i=0;i<4;i++){ float x=sM0[(n0+i)*SP+d];
            acc[i][0]=fmaf(x,w.x,acc[i][0]); acc[i][1]=fmaf(x,w.y,acc[i][1]);
            acc[i][2]=fmaf(x,w.z,acc[i][2]); acc[i][3]=fmaf(x,w.w,acc[i][3]); }
    }
    cpwaitall(); __syncthreads();
    #pragma unroll
    for(int i=0;i<4;i++)
        #pragma unroll
        for(int j=0;j<4;j++) sM0[(n0+i)*SP+e0+j]=ftanh(acc[i][j]);

    /* agg1: msg1 @ agg_w[1] (buf1), prefetch att_w[0] -> buf0 */
    prefW(swb, att_w, t);
    #pragma unroll
    for(int i=0;i<4;i++){ float4 bb=*(const float4*)&sB[64+e0];
        acc[i][0]=bb.x; acc[i][1]=bb.y; acc[i][2]=bb.z; acc[i][3]=bb.w; }
    #pragma unroll 4
    for(int d=0;d<64;d++){
        float4 w=*(const float4*)&sW[4096+d*64+e0];
        #pragma unroll
        for(int i=0;i<4;i++){ float x=sM1[(n0+i)*SP+d];
            acc[i][0]=fmaf(x,w.x,acc[i][0]); acc[i][1]=fmaf(x,w.y,acc[i][1]);
            acc[i][2]=fmaf(x,w.z,acc[i][2]); acc[i][3]=fmaf(x,w.w,acc[i][3]); }
    }
    cpwaitall(); __syncthreads();
    #pragma unroll
    for(int i=0;i<4;i++)
        #pragma unroll
        for(int j=0;j<4;j++) sM1[(n0+i)*SP+e0+j]=ftanh(acc[i][j]);

    /* att heads: W[h] in buf(h&1); prefetch next (h3 prefetches gwu) */
    for(int h=0;h<4;h++){
        const float* Wc=sW+(h&1)*4096;
        prefW(swb+((h&1)^1)*16384u, (h<3)? att_w+(h+1)*4096 : gwu, t);
        for(int k=0;k<2;k++){
            const float* X=(k==0)? sM0 : sM1;
            #pragma unroll
            for(int i=0;i<4;i++){ float4 bb=*(const float4*)&sB[128+h*64+e0];
                acc[i][0]=bb.x; acc[i][1]=bb.y; acc[i][2]=bb.z; acc[i][3]=bb.w; }
            #pragma unroll 4
            for(int d=0;d<64;d++){
                float4 w=*(const float4*)&Wc[d*64+e0];
                #pragma unroll
                for(int i=0;i<4;i++){ float x=X[(n0+i)*SP+d];
                    acc[i][0]=fmaf(x,w.x,acc[i][0]); acc[i][1]=fmaf(x,w.y,acc[i][1]);
                    acc[i][2]=fmaf(x,w.z,acc[i][2]); acc[i][3]=fmaf(x,w.w,acc[i][3]); }
            }
            float4 av=*(const float4*)&sB[384+h*64+e0];
            #pragma unroll
            for(int i=0;i<4;i++){
                float p=av.x*htanh(acc[i][0])+av.y*htanh(acc[i][1])
                       +av.z*htanh(acc[i][2])+av.w*htanh(acc[i][3]);
                sRed[(n0+i)*16+eq]=p;
            }
            __syncthreads();
            if(t<32){
                float s=0.f;
                #pragma unroll
                for(int q2=0;q2<16;q2++) s+=sRed[t*16+q2];
                sSc[(h*2+k)*32+t]=s;
            }
            if(k==1) cpwaitall();
            __syncthreads();
        }
    }
    /* buf0 = gwu (arrived) */

    if(t<32){
        float c0=0.f, c1=0.f;
        #pragma unroll
        for(int h=0;h<4;h++){
            float s0=sSc[(h*2)*32+t], s1=sSc[(h*2+1)*32+t];
            float m=fmaxf(s0,s1);
            float a=__expf(s0-m), bz=__expf(s1-m);
            float is=1.f/(a+bz);
            c0+=a*is; c1+=bz*is;
        }
        sCw[t]=c0*0.25f; sCw[32+t]=c1*0.25f;
    }
    __syncthreads();
    for(int i=t;i<TN*64;i+=128){
        int n=i>>6, e=i&63;
        sNxt[n*SP+e]=sCw[n]*sM0[n*SP+e]+sCw[32+n]*sM1[n*SP+e];
    }
    prefW(swb+16384u, gwu+4096, t);   /* gwu part2 -> buf1 */
    __syncthreads();

    /* GRU half-stage macro: compute acc += X·W(buf) over d */
#define GRU_HALF(XEXPR, WOFF) \
    { _Pragma("unroll 4") \
      for(int d=0;d<64;d++){ \
        float4 w=*(const float4*)&sW[(WOFF)+d*64+e0]; \
        _Pragma("unroll") \
        for(int i=0;i<4;i++){ float x=(XEXPR); \
            acc[i][0]=fmaf(x,w.x,acc[i][0]); acc[i][1]=fmaf(x,w.y,acc[i][1]); \
            acc[i][2]=fmaf(x,w.z,acc[i][2]); acc[i][3]=fmaf(x,w.w,acc[i][3]); } } }

    /* U gate: stages gwu(buf0), gwu2(buf1) */
    #pragma unroll
    for(int i=0;i<4;i++){ float4 bb=*(const float4*)&sB[640+e0];
        acc[i][0]=bb.x; acc[i][1]=bb.y; acc[i][2]=bb.z; acc[i][3]=bb.w; }
    GRU_HALF(sNxt[(n0+i)*SP+d], 0)
    cpwaitall(); __syncthreads();
    prefW(swb, gwr, t);
    GRU_HALF(sEnc[(n0+i)*SP+d], 4096)
    #pragma unroll
    for(int i=0;i<4;i++)
        #pragma unroll
        for(int j=0;j<4;j++) sM0[(n0+i)*SP+e0+j]=fsig(acc[i][j]);
    cpwaitall(); __syncthreads();

    /* R gate: gwr(buf0), gwr2(buf1) */
    prefW(swb+16384u, gwr+4096, t);
    #pragma unroll
    for(int i=0;i<4;i++){ float4 bb=*(const float4*)&sB[704+e0];
        acc[i][0]=bb.x; acc[i][1]=bb.y; acc[i][2]=bb.z; acc[i][3]=bb.w; }
    GRU_HALF(sNxt[(n0+i)*SP+d], 0)
    cpwaitall(); __syncthreads();
    prefW(swb, gwc, t);
    GRU_HALF(sEnc[(n0+i)*SP+d], 4096)
    #pragma unroll
    for(int i=0;i<4;i++)
        #pragma unroll
        for(int j=0;j<4;j++) sM1[(n0+i)*SP+e0+j]=fsig(acc[i][j]);
    cpwaitall(); __syncthreads();

    /* C candidate: gwc(buf0), gwc2(buf1) */
    prefW(swb+16384u, gwc+4096, t);
    #pragma unroll
    for(int i=0;i<4;i++){ float4 bb=*(const float4*)&sB[768+e0];
        acc[i][0]=bb.x; acc[i][1]=bb.y; acc[i][2]=bb.z; acc[i][3]=bb.w; }
    GRU_HALF(sNxt[(n0+i)*SP+d], 0)
    cpwaitall(); __syncthreads();
    GRU_HALF(sM1[(n0+i)*SP+d]*sEnc[(n0+i)*SP+d], 4096)
    #pragma unroll
    for(int i=0;i<4;i++){
        float4 o;
        #pragma unroll
        for(int j=0;j<4;j++){
            float c=ftanh(acc[i][j]);
            float u=sM0[(n0+i)*SP+e0+j];
            float ev=sEnc[(n0+i)*SP+e0+j];
            ((float*)&o)[j]=u*ev+(1.f-u)*c;
        }
        *(float4*)&g_enc[(base+n0+i)*64+e0]=o;
    }
#undef GRU_HALF
}

/* ---- per-node decoder dots ---- */
__global__ __launch_bounds__(256) void k_pred(){
    int gw=(blockIdx.x*256+threadIdx.x)>>5;
    if(gw>=NGT) return;
    int lane=threadIdx.x&31;
    float e1=g_enc[gw*64+lane], e2=g_enc[gw*64+32+lane];
    float p = e1*g_comb[lane]   + e2*g_comb[32+lane];
    float dv= e1*g_comb[66+lane]+ e2*g_comb[98+lane];
    #pragma unroll
    for(int o=16;o;o>>=1){ p+=__shfl_down_sync(0xffffffffu,p,o); dv+=__shfl_down_sync(0xffffffffu,dv,o); }
    if(lane==0){ g_pred[gw]=p+g_comb[64]; g_dualp[gw]=dv+g_comb[65]; }
}

/* ---- sparsemax per adjacency row + support edge list ---- */
__global__ __launch_bounds__(64) void k_smax(){
    int r=blockIdx.x, t=threadIdx.x;
    int b=r/VV, u=r%VV;
    int nnz=g_nnz[r];
    __shared__ float zb[64], zs[64], cum[64];
    __shared__ float wred[2];
    __shared__ int bases[2]; __shared__ int cnts[2];
    int col=(t<nnz)? g_cols[r*64+t] : 0;
    float z=(t<nnz)? g_pred[b*VV+col] : -3.0e38f;
    zb[t]=z; __syncthreads();
    int rank=0;
    #pragma unroll 8
    for(int k2=0;k2<64;k2++){
        float zk=zb[k2];
        rank += (zk>z) || (zk==z && k2<t);
    }
    zs[rank]=z; __syncthreads();
    if(t==0){ float c=0.f; for(int i=0;i<64;i++){ c+=zs[i]; cum[i]=c; } }
    __syncthreads();
    int sup=(t<nnz) && (zs[t]*(float)(t+1) > cum[t]-1.0f);
    int ksel=__syncthreads_count(sup);
    float p=0.f;
    if(nnz>0 && t<nnz){
        float tau=(cum[ksel-1]-1.0f)/(float)ksel;
        p=fmaxf(z-tau,0.f);
    }
    float q=p*p;
    #pragma unroll
    for(int o=16;o;o>>=1) q+=__shfl_down_sync(0xffffffffu,q,o);
    if((t&31)==0) wred[t>>5]=q;
    __syncthreads();
    if(t==0) g_rowss[r]=wred[0]+wred[1];
    int w=t>>5, lane=t&31;
    unsigned m=__ballot_sync(0xffffffffu, p>0.f);
    if(lane==0) cnts[w]=__popc(m);
    __syncthreads();
    if(t==0){
        int tot=cnts[0]+cnts[1];
        int be=atomicAdd(&g_ecnt[b], tot);
        bases[0]=be; bases[1]=be+cnts[0];
    }
    __syncthreads();
    if(p>0.f){
        int slot=bases[w]+__popc(m & ((1u<<lane)-1u));
        g_eu[b*EMAX+slot]=u; g_ev[b*EMAX+slot]=col; g_ep[b*EMAX+slot]=p;
    }
}

/* ---- primal min-cost-flow: a <- relu(P^T a - dem), 7 updates ---- */
__global__ __launch_bounds__(1024) void k_flow(const float* __restrict__ dem){
    __shared__ float sa[VV];
    __shared__ float si[VV];
    __shared__ float red[32];
    int b=blockIdx.x, t=threadIdx.x;
    for(int u=t;u<VV;u+=1024) sa[u]=fmaxf(-dem[b*VV+u],0.f);
    int ec=g_ecnt[b];
    for(int it=0;it<7;it++){
        for(int v=t;v<VV;v+=1024) si[v]=0.f;
        __syncthreads();
        for(int e=t;e<ec;e+=1024){
            float a=sa[g_eu[b*EMAX+e]];
            if(a>0.f) atomicAdd(&si[g_ev[b*EMAX+e]], g_ep[b*EMAX+e]*a);
        }
        __syncthreads();
        for(int v=t;v<VV;v+=1024) sa[v]=fmaxf(si[v]-dem[b*VV+v],0.f);
        __syncthreads();
    }
    float c=0.f;
    for(int u=t;u<VV;u+=1024){ float a=sa[u]; c=fmaf(a*a,g_rowss[b*VV+u],c); }
    #pragma unroll
    for(int o=16;o;o>>=1) c+=__shfl_down_sync(0xffffffffu,c,o);
    if((t&31)==0) red[t>>5]=c;
    __syncthreads();
    if(t==0){ float s=0.f; for(int i=0;i<32;i++) s+=red[i]; g_flowcost[b]=s; }
}

/* ---- dual flow: warp per row, 8-step Nesterov recurrence per edge ---- */
__global__ __launch_bounds__(256) void k_dual(){
    int wr=(blockIdx.x*256+threadIdx.x)>>5;
    if(wr>=NGT) return;
    int lane=threadIdx.x&31;
    int b=wr/VV, u=wr%VV;
    int nnz=g_nnz[wr];
    float contrib=0.f;
    for(int j=lane;j<nnz;j+=32){
        int v=g_cols[wr*64+j];
        float dd=g_dualp[b*VV+u]-g_dualp[b*VV+v];
        float flow=0.f, acc=0.f;
        #pragma unroll
        for(int i=0;i<8;i++){
            float look=flow-0.9f*acc;
            float grad=2.f*look-dd;
            acc=0.9f*acc+0.1f*grad;
            flow=fmaxf(flow-acc,0.f);
        }
        contrib+=flow*flow-dd*flow;
    }
    #pragma unroll
    for(int o=16;o;o>>=1) contrib+=__shfl_down_sync(0xffffffffu,contrib,o);
    if(lane==0 && contrib!=0.f) atomicAdd(&g_dualedge[b], contrib);
}

/* ---- final: out[b] = flow_cost - dual_edge + dual_demand ---- */
__global__ __launch_bounds__(256) void k_final(const float* __restrict__ dem, float* __restrict__ out){
    int b=blockIdx.x, t=threadIdx.x;
    __shared__ float red[8];
    float s=0.f;
    for(int v=t;v<VV;v+=256) s=fmaf(g_dualp[b*VV+v],dem[b*VV+v],s);
    #pragma unroll
    for(int o=16;o;o>>=1) s+=__shfl_down_sync(0xffffffffu,s,o);
    if((t&31)==0) red[t>>5]=s;
    __syncthreads();
    if(t==0){
        float tot=0.f;
        #pragma unroll
        for(int i=0;i<8;i++) tot+=red[i];
        out[b]=g_flowcost[b]-g_dualedge[b]+tot;
    }
}

extern "C" void kernel_launch(void* const* d_in, const int* in_sizes, int n_in,
                              void* d_out, int out_size) {
    const float* feat  =(const float*)d_in[0];
    const float* emb   =(const float*)d_in[1];
    const float* dem   =(const float*)d_in[2];
    const float* adj   =(const float*)d_in[3];
    const float* nb    =(const float*)d_in[4];
    const float* enc_w0=(const float*)d_in[5];
    const float* enc_b0=(const float*)d_in[6];
    const float* enc_w1=(const float*)d_in[7];
    const float* enc_b1=(const float*)d_in[8];
    const float* agg_w =(const float*)d_in[9];
    const float* agg_b =(const float*)d_in[10];
    const float* att_w =(const float*)d_in[11];
    const float* att_b =(const float*)d_in[12];
    const float* att_v =(const float*)d_in[13];
    const float* gwu   =(const float*)d_in[14];
    const float* gbu   =(const float*)d_in[15];
    const float* gwr   =(const float*)d_in[16];
    const float* gbr   =(const float*)d_in[17];
    const float* gwc   =(const float*)d_in[18];
    const float* gbc   =(const float*)d_in[19];
    const float* dec_w0=(const float*)d_in[20];
    const float* dec_b0=(const float*)d_in[21];
    const float* dec_w1=(const float*)d_in[22];
    const float* dec_b1=(const float*)d_in[23];
    const float* dual_w0=(const float*)d_in[24];
    const float* dual_b0=(const float*)d_in[25];
    const float* dual_w1=(const float*)d_in[26];
    const float* dual_b1=(const float*)d_in[27];
    float* out=(float*)d_out;

    cudaFuncSetAttribute(k_node, cudaFuncAttributeMaxDynamicSharedMemorySize, SMB);
    cudaFuncSetAttribute(k_msg,  cudaFuncAttributeMaxDynamicSharedMemorySize, 2*TS*64*4);

    k_comb<<<1,64>>>(dec_w0,dec_b0,dec_w1,dec_b1,dual_w0,dual_b0,dual_w1,dual_b1);
    k_enc<<<NGT/TN,128>>>(feat,emb,enc_w0,enc_b0,enc_w1,enc_b1);
    k_csr_nb<<<2*NGT/8,256>>>(nb);
    k_csr_adj<<<NGT/8,256>>>(adj);
    for(int layer=0;layer<2;layer++){
        k_msg<<<dim3(VV/RB,BB),256,2*TS*64*4>>>();
        k_node<<<NGT/TN,128,SMB>>>(agg_w,agg_b,att_w,att_b,att_v,
                                   gwu,gbu,gwr,gbr,gwc,gbc);
    }
    k_pred<<<NGT/8,256>>>();
    k_smax<<<NGT,64>>>();
    k_flow<<<BB,1024>>>(dem);
    k_dual<<<NGT/8,256>>>();
    k_final<<<BB,256>>>(dem,out);
}

// round 17
// speedup vs baseline: 1.1702x; 1.1702x over previous
#include <cuda_runtime.h>

#define BB   8
#define VV   1200
#define NGT  (BB*VV)
#define TN   32
#define SP   65
#define EMAX 76800
#define NBCAP 640
#define TS   192          /* enc tile rows for msg (48KB smem) */
#define NTILE 7           /* ceil(1200/192) */
#define RW   3            /* dest nodes per warp in k_msg */
#define RB   24           /* dest nodes per block (8 warps * 3) */

__device__ float g_enc[NGT*64];
__device__ float g_msg[2*NGT*64];
__device__ float g_pred[NGT];
__device__ float g_dualp[NGT];
__device__ int   g_cols[NGT*64];
__device__ int   g_nnz[NGT];
__device__ float g_rowss[NGT];
__device__ int   g_nbcols[2*NGT*NBCAP];
__device__ int   g_nbnnz[2*NGT];
__device__ float g_nbinv[2*NGT];
__device__ int   g_nbseg[2*NGT*8];
__device__ int   g_eu[BB*EMAX];
__device__ int   g_ev[BB*EMAX];
__device__ float g_ep[BB*EMAX];
__device__ int   g_ecnt[BB];
__device__ float g_dualedge[BB];
__device__ float g_flowcost[BB];
__device__ float g_comb[132];

__device__ __forceinline__ float ftanh(float x){ float e=__expf(2.f*x); return 1.f-2.f/(e+1.f); }
__device__ __forceinline__ float fsig (float x){ return 1.f/(1.f+__expf(-x)); }
/* HW tanh: 1 MUFU op, ~6e-4 abs err — attention score path only */
__device__ __forceinline__ float htanh(float x){
    float y; asm("tanh.approx.f32 %0,%1;":"=f"(y):"f"(x)); return y;
}

__device__ __forceinline__ unsigned smem_u32(const void* p){
    unsigned r;
    asm("{ .reg .u64 t; cvta.to.shared.u64 t, %1; cvt.u32.u64 %0, t; }":"=r"(r):"l"(p));
    return r;
}
__device__ __forceinline__ void cpa16(unsigned dst, const float* src){
    asm volatile("cp.async.cg.shared.global [%0],[%1],16;"::"r"(dst),"l"(src));
}
__device__ __forceinline__ void cpcommit(){ asm volatile("cp.async.commit_group;":::"memory"); }
__device__ __forceinline__ void cpwaitall(){ asm volatile("cp.async.wait_all;":::"memory"); }
__device__ __forceinline__ void prefW(unsigned sdst, const float* W, int t){
    #pragma unroll
    for(int i=0;i<8;i++) cpa16(sdst + (unsigned)(t + i*128)*16u, W + (t + i*128)*4);
    cpcommit();
}

/* ---- collapse decoder MLPs + zero accumulators ---- */
__global__ void k_comb(const float* __restrict__ w0,const float* __restrict__ b0,
                       const float* __restrict__ w1,const float* __restrict__ b1,
                       const float* __restrict__ dw0,const float* __restrict__ db0,
                       const float* __restrict__ dw1,const float* __restrict__ db1){
    int d=threadIdx.x;
    if(d<BB){ g_ecnt[d]=0; g_dualedge[d]=0.f; }
    float s=0.f, sd=0.f;
    for(int e=0;e<64;e++){ s+=w0[d*64+e]*w1[e]; sd+=dw0[d*64+e]*dw1[e]; }
    g_comb[d]=s; g_comb[66+d]=sd;
    if(d==0){
        float bb=b1[0], bd=db1[0];
        for(int e=0;e<64;e++){ bb+=b0[e]*w1[e]; bd+=db0[e]*dw1[e]; }
        g_comb[64]=bb; g_comb[65]=bd;
    }
}

/* ---- encoder: enc = tanh(tanh(x W0 + b0) W1 + b1), x=[emb16,feat8] ---- */
__global__ __launch_bounds__(128) void k_enc(
        const float* __restrict__ feat, const float* __restrict__ emb,
        const float* __restrict__ w0, const float* __restrict__ b0,
        const float* __restrict__ w1, const float* __restrict__ b1){
    __shared__ __align__(16) float sW0[24*64];
    __shared__ __align__(16) float sW1[64*64];
    __shared__ __align__(16) float sB[128];
    __shared__ __align__(16) float sX[TN*24];
    __shared__ __align__(16) float sH[TN*SP];
    int t=threadIdx.x;
    int base=blockIdx.x*TN;
    for(int i=t;i<384;i+=128)  ((float4*)sW0)[i]=((const float4*)w0)[i];
    for(int i=t;i<1024;i+=128) ((float4*)sW1)[i]=((const float4*)w1)[i];
    if(t<64){ sB[t]=b0[t]; sB[64+t]=b1[t]; }
    for(int i=t;i<TN*24;i+=128){
        int n=i/24, d=i%24, g=base+n;
        sX[i]=(d<16)? emb[g*16+d] : feat[g*8+(d-16)];
    }
    __syncthreads();
    const int eq=t&15, ng=t>>4, e0=eq*4, n0=ng*4;
    float acc[4][4];
    #pragma unroll
    for(int i=0;i<4;i++){ float4 bb=*(const float4*)&sB[e0];
        acc[i][0]=bb.x; acc[i][1]=bb.y; acc[i][2]=bb.z; acc[i][3]=bb.w; }
    for(int d=0;d<24;d++){
        float4 w=*(const float4*)&sW0[d*64+e0];
        #pragma unroll
        for(int i=0;i<4;i++){ float x=sX[(n0+i)*24+d];
            acc[i][0]=fmaf(x,w.x,acc[i][0]); acc[i][1]=fmaf(x,w.y,acc[i][1]);
            acc[i][2]=fmaf(x,w.z,acc[i][2]); acc[i][3]=fmaf(x,w.w,acc[i][3]); }
    }
    #pragma unroll
    for(int i=0;i<4;i++)
        #pragma unroll
        for(int j=0;j<4;j++) sH[(n0+i)*SP+e0+j]=ftanh(acc[i][j]);
    __syncthreads();
    #pragma unroll
    for(int i=0;i<4;i++){ float4 bb=*(const float4*)&sB[64+e0];
        acc[i][0]=bb.x; acc[i][1]=bb.y; acc[i][2]=bb.z; acc[i][3]=bb.w; }
    #pragma unroll 4
    for(int d=0;d<64;d++){
        float4 w=*(const float4*)&sW1[d*64+e0];
        #pragma unroll
        for(int i=0;i<4;i++){ float x=sH[(n0+i)*SP+d];
            acc[i][0]=fmaf(x,w.x,acc[i][0]); acc[i][1]=fmaf(x,w.y,acc[i][1]);
            acc[i][2]=fmaf(x,w.z,acc[i][2]); acc[i][3]=fmaf(x,w.w,acc[i][3]); }
    }
    #pragma unroll
    for(int i=0;i<4;i++){
        float4 o; o.x=ftanh(acc[i][0]); o.y=ftanh(acc[i][1]);
        o.z=ftanh(acc[i][2]); o.w=ftanh(acc[i][3]);
        *(float4*)&g_enc[(base+n0+i)*64+e0]=o;
    }
}

/* ---- CSR compaction with BATCHED loads (MLP=10) then ballot prefix ----
   All 10 float4 row-chunks load into registers first (independent, deep MLP),
   flags packed 4-bit; ballot/compaction loop then runs register-resident. */
__device__ __forceinline__ void csr_row_batched(const float* __restrict__ row,
                                                int* __restrict__ outCols, int cap,
                                                int lane, int* outCnt){
    const float4* r4=(const float4*)row;
    unsigned lt=(1u<<lane)-1u;
    int flg[10];
    #pragma unroll
    for(int c=0;c<10;c++){
        int i=c*32+lane;
        float4 v=(i<300)? r4[i] : make_float4(0.f,0.f,0.f,0.f);
        flg[c]=(v.x!=0.f) | ((v.y!=0.f)<<1) | ((v.z!=0.f)<<2) | ((v.w!=0.f)<<3);
    }
    int cnt=0;
    #pragma unroll
    for(int c=0;c<10;c++){
        int f=flg[c];
        unsigned m0=__ballot_sync(0xffffffffu, f&1);
        unsigned m1=__ballot_sync(0xffffffffu, f&2);
        unsigned m2=__ballot_sync(0xffffffffu, f&4);
        unsigned m3=__ballot_sync(0xffffffffu, f&8);
        int base=cnt + __popc(m0&lt)+__popc(m1&lt)+__popc(m2&lt)+__popc(m3&lt);
        int col0=(c*32+lane)*4;
        if(f&1){ if(base<cap) outCols[base]=col0;   base++; }
        if(f&2){ if(base<cap) outCols[base]=col0+1; base++; }
        if(f&4){ if(base<cap) outCols[base]=col0+2; base++; }
        if(f&8){ if(base<cap) outCols[base]=col0+3; base++; }
        cnt += __popc(m0)+__popc(m1)+__popc(m2)+__popc(m3);
    }
    *outCnt=cnt;
}

/* fused CSR build: wr < NGT -> adj row; else neighborhood row (wr-NGT) */
__global__ __launch_bounds__(256) void k_csr(const float* __restrict__ adj,
                                             const float* __restrict__ nb){
    int wr=(blockIdx.x*blockDim.x+threadIdx.x)>>5;
    if(wr>=3*NGT) return;
    int lane=threadIdx.x&31;
    if(wr<NGT){
        int cnt;
        csr_row_batched(adj+(size_t)wr*VV, &g_cols[wr*64], 64, lane, &cnt);
        if(lane==0) g_nnz[wr]=min(cnt,64);
    }else{
        int r=wr-NGT;               /* 0 .. 2*NGT-1 */
        int cnt;
        const int* cols=&g_nbcols[(size_t)r*NBCAP];
        csr_row_batched(nb+(size_t)r*VV, &g_nbcols[(size_t)r*NBCAP], NBCAP, lane, &cnt);
        int nnzc=min(cnt,NBCAP);
        if(lane<8){
            int sg;
            if(lane==0) sg=0;
            else if(lane==7) sg=nnzc;
            else{
                int key=lane*TS, lo=0, hi=nnzc;
                while(lo<hi){ int m=(lo+hi)>>1; if(cols[m]<key) lo=m+1; else hi=m; }
                sg=lo;
            }
            g_nbseg[r*8+lane]=sg;
        }
        if(lane==0){
            g_nbnnz[r]=nnzc;
            g_nbinv[r]=1.f/fmaxf((float)cnt,1.f);
        }
    }
}

/* ---- both-hop msg: smem-tiled SpMM, zero searching (seg offsets) ---- */
__global__ __launch_bounds__(256) void k_msg(){
    extern __shared__ __align__(16) float sT[];    /* TS*64 floats = 48 KB */
    int t=threadIdx.x, lane=t&31, w=t>>5;
    int b=blockIdx.y;
    int v0=blockIdx.x*RB + w*RW;

    float2 acc[2][RW];
    #pragma unroll
    for(int hp=0;hp<2;hp++)
        #pragma unroll
        for(int s=0;s<RW;s++) acc[hp][s]=make_float2(0.f,0.f);

    for(int tile=0;tile<NTILE;tile++){
        int tLo=tile*TS;
        int ts=min(TS,VV-tLo);
        __syncthreads();
        {   const float4* src=(const float4*)&g_enc[(size_t)(b*VV+tLo)*64];
            float4* dst=(float4*)sT;
            int n4=ts*16;
            for(int i=t;i<n4;i+=256) dst[i]=src[i];
        }
        __syncthreads();
        #pragma unroll
        for(int hp=0;hp<2;hp++){
            #pragma unroll
            for(int s=0;s<RW;s++){
                int r=hp*NGT + b*VV + v0+s;
                int lo=g_nbseg[r*8+tile];
                int hi=g_nbseg[r*8+tile+1];
                const int* cl=&g_nbcols[(size_t)r*NBCAP];
                float2 a=acc[hp][s];
                int j=lo;
                for(; j+3<hi; j+=4){
                    int c0=cl[j]-tLo, c1=cl[j+1]-tLo, c2=cl[j+2]-tLo, c3=cl[j+3]-tLo;
                    float2 e0=*(const float2*)&sT[c0*64+lane*2];
                    float2 e1=*(const float2*)&sT[c1*64+lane*2];
                    float2 e2=*(const float2*)&sT[c2*64+lane*2];
                    float2 e3=*(const float2*)&sT[c3*64+lane*2];
                    a.x+=e0.x+e1.x+e2.x+e3.x;
                    a.y+=e0.y+e1.y+e2.y+e3.y;
                }
                for(; j<hi; j++){
                    int c=cl[j]-tLo;
                    float2 e=*(const float2*)&sT[c*64+lane*2];
                    a.x+=e.x; a.y+=e.y;
                }
                acc[hp][s]=a;
            }
        }
    }
    #pragma unroll
    for(int hp=0;hp<2;hp++)
        #pragma unroll
        for(int s=0;s<RW;s++){
            int r=hp*NGT + b*VV + v0+s;
            float inv=g_nbinv[r];
            float2 o; o.x=acc[hp][s].x*inv; o.y=acc[hp][s].y*inv;
            *(float2*)&g_msg[(size_t)r*64+lane*2]=o;
        }
}

/* ---- fused graph layer: agg -> hop attention -> GRU, cp.async W pipeline -- */
#define SMF (4*TN*SP + 2*4096 + 512 + 256 + 64 + 832)
#define SMB (SMF*4)

__global__ __launch_bounds__(128) void k_node(
        const float* __restrict__ agg_w, const float* __restrict__ agg_b,
        const float* __restrict__ att_w, const float* __restrict__ att_b,
        const float* __restrict__ att_v,
        const float* __restrict__ gwu, const float* __restrict__ gbu,
        const float* __restrict__ gwr, const float* __restrict__ gbr,
        const float* __restrict__ gwc, const float* __restrict__ gbc){
    extern __shared__ __align__(16) float sm[];
    float* sEnc=sm;
    float* sM0 =sEnc+TN*SP;
    float* sM1 =sM0 +TN*SP;
    float* sNxt=sM1 +TN*SP;
    float* sW  =sNxt+TN*SP;      /* 2 x 4096 */
    float* sRed=sW+8192;
    float* sSc =sRed+512;
    float* sCw =sSc+256;
    float* sB  =sCw+64;

    int t=threadIdx.x;
    int base=blockIdx.x*TN;
    const int eq=t&15, ng=t>>4, e0=eq*4, n0=ng*4;
    unsigned swb=smem_u32(sW);

    prefW(swb, agg_w, t);                              /* stage0 W -> buf0 */

    for(int i=t;i<TN*64;i+=128){
        int n=i>>6, e=i&63;
        sEnc[n*SP+e]=g_enc[(base+n)*64+e];
        sM0 [n*SP+e]=g_msg[(size_t)(base+n)*64+e];
        sM1 [n*SP+e]=g_msg[(size_t)(NGT+base+n)*64+e];
    }
    if(t<128) sB[t]=agg_b[t];
    for(int i=t;i<256;i+=128){ sB[128+i]=att_b[i]; sB[384+i]=att_v[i]; }
    if(t<64){ sB[640+t]=gbu[t]; sB[704+t]=gbr[t]; sB[768+t]=gbc[t]; }
    cpwaitall(); __syncthreads();

    float acc[4][4];

    /* agg0: msg0 @ agg_w[0], prefetch agg_w[1] */
    prefW(swb+16384u, agg_w+4096, t);
    #pragma unroll
    for(int i=0;i<4;i++){ float4 bb=*(const float4*)&sB[e0];
        acc[i][0]=bb.x; acc[i][1]=bb.y; acc[i][2]=bb.z; acc[i][3]=bb.w; }
    #pragma unroll 4
    for(int d=0;d<64;d++){
        float4 w=*(const float4*)&sW[d*64+e0];
        #pragma unroll
        for(int i=0;i<4;i++){ float x=sM0[(n0+i)*SP+d];
            acc[i][0]=fmaf(x,w.x,acc[i][0]); acc[i][1]=fmaf(x,w.y,acc[i][1]);
            acc[i][2]=fmaf(x,w.z,acc[i][2]); acc[i][3]=fmaf(x,w.w,acc[i][3]); }
    }
    cpwaitall(); __syncthreads();
    #pragma unroll
    for(int i=0;i<4;i++)
        #pragma unroll
        for(int j=0;j<4;j++) sM0[(n0+i)*SP+e0+j]=ftanh(acc[i][j]);

    /* agg1: msg1 @ agg_w[1] (buf1), prefetch att_w[0] -> buf0 */
    prefW(swb, att_w, t);
    #pragma unroll
    for(int i=0;i<4;i++){ float4 bb=*(const float4*)&sB[64+e0];
        acc[i][0]=bb.x; acc[i][1]=bb.y; acc[i][2]=bb.z; acc[i][3]=bb.w; }
    #pragma unroll 4
    for(int d=0;d<64;d++){
        float4 w=*(const float4*)&sW[4096+d*64+e0];
        #pragma unroll
        for(int i=0;i<4;i++){ float x=sM1[(n0+i)*SP+d];
            acc[i][0]=fmaf(x,w.x,acc[i][0]); acc[i][1]=fmaf(x,w.y,acc[i][1]);
            acc[i][2]=fmaf(x,w.z,acc[i][2]); acc[i][3]=fmaf(x,w.w,acc[i][3]); }
    }
    cpwaitall(); __syncthreads();
    #pragma unroll
    for(int i=0;i<4;i++)
        #pragma unroll
        for(int j=0;j<4;j++) sM1[(n0+i)*SP+e0+j]=ftanh(acc[i][j]);

    /* att heads: W[h] in buf(h&1); prefetch next (h3 prefetches gwu) */
    for(int h=0;h<4;h++){
        const float* Wc=sW+(h&1)*4096;
        prefW(swb+((h&1)^1)*16384u, (h<3)? att_w+(h+1)*4096 : gwu, t);
        for(int k=0;k<2;k++){
            const float* X=(k==0)? sM0 : sM1;
            #pragma unroll
            for(int i=0;i<4;i++){ float4 bb=*(const float4*)&sB[128+h*64+e0];
                acc[i][0]=bb.x; acc[i][1]=bb.y; acc[i][2]=bb.z; acc[i][3]=bb.w; }
            #pragma unroll 4
            for(int d=0;d<64;d++){
                float4 w=*(const float4*)&Wc[d*64+e0];
                #pragma unroll
                for(int i=0;i<4;i++){ float x=X[(n0+i)*SP+d];
                    acc[i][0]=fmaf(x,w.x,acc[i][0]); acc[i][1]=fmaf(x,w.y,acc[i][1]);
                    acc[i][2]=fmaf(x,w.z,acc[i][2]); acc[i][3]=fmaf(x,w.w,acc[i][3]); }
            }
            float4 av=*(const float4*)&sB[384+h*64+e0];
            #pragma unroll
            for(int i=0;i<4;i++){
                float p=av.x*htanh(acc[i][0])+av.y*htanh(acc[i][1])
                       +av.z*htanh(acc[i][2])+av.w*htanh(acc[i][3]);
                sRed[(n0+i)*16+eq]=p;
            }
            __syncthreads();
            if(t<32){
                float s=0.f;
                #pragma unroll
                for(int q2=0;q2<16;q2++) s+=sRed[t*16+q2];
                sSc[(h*2+k)*32+t]=s;
            }
            if(k==1) cpwaitall();
            __syncthreads();
        }
    }
    /* buf0 = gwu (arrived) */

    if(t<32){
        float c0=0.f, c1=0.f;
        #pragma unroll
        for(int h=0;h<4;h++){
            float s0=sSc[(h*2)*32+t], s1=sSc[(h*2+1)*32+t];
            float m=fmaxf(s0,s1);
            float a=__expf(s0-m), bz=__expf(s1-m);
            float is=1.f/(a+bz);
            c0+=a*is; c1+=bz*is;
        }
        sCw[t]=c0*0.25f; sCw[32+t]=c1*0.25f;
    }
    __syncthreads();
    for(int i=t;i<TN*64;i+=128){
        int n=i>>6, e=i&63;
        sNxt[n*SP+e]=sCw[n]*sM0[n*SP+e]+sCw[32+n]*sM1[n*SP+e];
    }
    prefW(swb+16384u, gwu+4096, t);   /* gwu part2 -> buf1 */
    __syncthreads();

    /* GRU half-stage macro: compute acc += X·W(buf) over d */
#define GRU_HALF(XEXPR, WOFF) \
    { _Pragma("unroll 4") \
      for(int d=0;d<64;d++){ \
        float4 w=*(const float4*)&sW[(WOFF)+d*64+e0]; \
        _Pragma("unroll") \
        for(int i=0;i<4;i++){ float x=(XEXPR); \
            acc[i][0]=fmaf(x,w.x,acc[i][0]); acc[i][1]=fmaf(x,w.y,acc[i][1]); \
            acc[i][2]=fmaf(x,w.z,acc[i][2]); acc[i][3]=fmaf(x,w.w,acc[i][3]); } } }

    /* U gate: stages gwu(buf0), gwu2(buf1) */
    #pragma unroll
    for(int i=0;i<4;i++){ float4 bb=*(const float4*)&sB[640+e0];
        acc[i][0]=bb.x; acc[i][1]=bb.y; acc[i][2]=bb.z; acc[i][3]=bb.w; }
    GRU_HALF(sNxt[(n0+i)*SP+d], 0)
    cpwaitall(); __syncthreads();
    prefW(swb, gwr, t);
    GRU_HALF(sEnc[(n0+i)*SP+d], 4096)
    #pragma unroll
    for(int i=0;i<4;i++)
        #pragma unroll
        for(int j=0;j<4;j++) sM0[(n0+i)*SP+e0+j]=fsig(acc[i][j]);
    cpwaitall(); __syncthreads();

    /* R gate: gwr(buf0), gwr2(buf1) */
    prefW(swb+16384u, gwr+4096, t);
    #pragma unroll
    for(int i=0;i<4;i++){ float4 bb=*(const float4*)&sB[704+e0];
        acc[i][0]=bb.x; acc[i][1]=bb.y; acc[i][2]=bb.z; acc[i][3]=bb.w; }
    GRU_HALF(sNxt[(n0+i)*SP+d], 0)
    cpwaitall(); __syncthreads();
    prefW(swb, gwc, t);
    GRU_HALF(sEnc[(n0+i)*SP+d], 4096)
    #pragma unroll
    for(int i=0;i<4;i++)
        #pragma unroll
        for(int j=0;j<4;j++) sM1[(n0+i)*SP+e0+j]=fsig(acc[i][j]);
    cpwaitall(); __syncthreads();

    /* C candidate: gwc(buf0), gwc2(buf1) */
    prefW(swb+16384u, gwc+4096, t);
    #pragma unroll
    for(int i=0;i<4;i++){ float4 bb=*(const float4*)&sB[768+e0];
        acc[i][0]=bb.x; acc[i][1]=bb.y; acc[i][2]=bb.z; acc[i][3]=bb.w; }
    GRU_HALF(sNxt[(n0+i)*SP+d], 0)
    cpwaitall(); __syncthreads();
    GRU_HALF(sM1[(n0+i)*SP+d]*sEnc[(n0+i)*SP+d], 4096)
    #pragma unroll
    for(int i=0;i<4;i++){
        float4 o;
        #pragma unroll
        for(int j=0;j<4;j++){
            float c=ftanh(acc[i][j]);
            float u=sM0[(n0+i)*SP+e0+j];
            float ev=sEnc[(n0+i)*SP+e0+j];
            ((float*)&o)[j]=u*ev+(1.f-u)*c;
        }
        *(float4*)&g_enc[(base+n0+i)*64+e0]=o;
    }
#undef GRU_HALF
}

/* ---- per-node decoder dots ---- */
__global__ __launch_bounds__(256) void k_pred(){
    int gw=(blockIdx.x*256+threadIdx.x)>>5;
    if(gw>=NGT) return;
    int lane=threadIdx.x&31;
    float e1=g_enc[gw*64+lane], e2=g_enc[gw*64+32+lane];
    float p = e1*g_comb[lane]   + e2*g_comb[32+lane];
    float dv= e1*g_comb[66+lane]+ e2*g_comb[98+lane];
    #pragma unroll
    for(int o=16;o;o>>=1){ p+=__shfl_down_sync(0xffffffffu,p,o); dv+=__shfl_down_sync(0xffffffffu,dv,o); }
    if(lane==0){ g_pred[gw]=p+g_comb[64]; g_dualp[gw]=dv+g_comb[65]; }
}

/* ---- sparsemax per adjacency row + support edge list ---- */
__global__ __launch_bounds__(64) void k_smax(){
    int r=blockIdx.x, t=threadIdx.x;
    int b=r/VV, u=r%VV;
    int nnz=g_nnz[r];
    __shared__ float zb[64], zs[64], cum[64];
    __shared__ float wred[2];
    __shared__ int bases[2]; __shared__ int cnts[2];
    int col=(t<nnz)? g_cols[r*64+t] : 0;
    float z=(t<nnz)? g_pred[b*VV+col] : -3.0e38f;
    zb[t]=z; __syncthreads();
    int rank=0;
    #pragma unroll 8
    for(int k2=0;k2<64;k2++){
        float zk=zb[k2];
        rank += (zk>z) || (zk==z && k2<t);
    }
    zs[rank]=z; __syncthreads();
    if(t==0){ float c=0.f; for(int i=0;i<64;i++){ c+=zs[i]; cum[i]=c; } }
    __syncthreads();
    int sup=(t<nnz) && (zs[t]*(float)(t+1) > cum[t]-1.0f);
    int ksel=__syncthreads_count(sup);
    float p=0.f;
    if(nnz>0 && t<nnz){
        float tau=(cum[ksel-1]-1.0f)/(float)ksel;
        p=fmaxf(z-tau,0.f);
    }
    float q=p*p;
    #pragma unroll
    for(int o=16;o;o>>=1) q+=__shfl_down_sync(0xffffffffu,q,o);
    if((t&31)==0) wred[t>>5]=q;
    __syncthreads();
    if(t==0) g_rowss[r]=wred[0]+wred[1];
    int w=t>>5, lane=t&31;
    unsigned m=__ballot_sync(0xffffffffu, p>0.f);
    if(lane==0) cnts[w]=__popc(m);
    __syncthreads();
    if(t==0){
        int tot=cnts[0]+cnts[1];
        int be=atomicAdd(&g_ecnt[b], tot);
        bases[0]=be; bases[1]=be+cnts[0];
    }
    __syncthreads();
    if(p>0.f){
        int slot=bases[w]+__popc(m & ((1u<<lane)-1u));
        g_eu[b*EMAX+slot]=u; g_ev[b*EMAX+slot]=col; g_ep[b*EMAX+slot]=p;
    }
}

/* ---- primal min-cost-flow: a <- relu(P^T a - dem), 7 updates ---- */
__global__ __launch_bounds__(1024) void k_flow(const float* __restrict__ dem){
    __shared__ float sa[VV];
    __shared__ float si[VV];
    __shared__ float red[32];
    int b=blockIdx.x, t=threadIdx.x;
    for(int u=t;u<VV;u+=1024) sa[u]=fmaxf(-dem[b*VV+u],0.f);
    int ec=g_ecnt[b];
    for(int it=0;it<7;it++){
        for(int v=t;v<VV;v+=1024) si[v]=0.f;
        __syncthreads();
        for(int e=t;e<ec;e+=1024){
            float a=sa[g_eu[b*EMAX+e]];
            if(a>0.f) atomicAdd(&si[g_ev[b*EMAX+e]], g_ep[b*EMAX+e]*a);
        }
        __syncthreads();
        for(int v=t;v<VV;v+=1024) sa[v]=fmaxf(si[v]-dem[b*VV+v],0.f);
        __syncthreads();
    }
    float c=0.f;
    for(int u=t;u<VV;u+=1024){ float a=sa[u]; c=fmaf(a*a,g_rowss[b*VV+u],c); }
    #pragma unroll
    for(int o=16;o;o>>=1) c+=__shfl_down_sync(0xffffffffu,c,o);
    if((t&31)==0) red[t>>5]=c;
    __syncthreads();
    if(t==0){ float s=0.f; for(int i=0;i<32;i++) s+=red[i]; g_flowcost[b]=s; }
}

/* ---- dual flow: warp per row, 8-step Nesterov recurrence per edge ---- */
__global__ __launch_bounds__(256) void k_dual(){
    int wr=(blockIdx.x*256+threadIdx.x)>>5;
    if(wr>=NGT) return;
    int lane=threadIdx.x&31;
    int b=wr/VV, u=wr%VV;
    int nnz=g_nnz[wr];
    float contrib=0.f;
    for(int j=lane;j<nnz;j+=32){
        int v=g_cols[wr*64+j];
        float dd=g_dualp[b*VV+u]-g_dualp[b*VV+v];
        float flow=0.f, acc=0.f;
        #pragma unroll
        for(int i=0;i<8;i++){
            float look=flow-0.9f*acc;
            float grad=2.f*look-dd;
            acc=0.9f*acc+0.1f*grad;
            flow=fmaxf(flow-acc,0.f);
        }
        contrib+=flow*flow-dd*flow;
    }
    #pragma unroll
    for(int o=16;o;o>>=1) contrib+=__shfl_down_sync(0xffffffffu,contrib,o);
    if(lane==0 && contrib!=0.f) atomicAdd(&g_dualedge[b], contrib);
}

/* ---- final: out[b] = flow_cost - dual_edge + dual_demand ---- */
__global__ __launch_bounds__(256) void k_final(const float* __restrict__ dem, float* __restrict__ out){
    int b=blockIdx.x, t=threadIdx.x;
    __shared__ float red[8];
    float s=0.f;
    for(int v=t;v<VV;v+=256) s=fmaf(g_dualp[b*VV+v],dem[b*VV+v],s);
    #pragma unroll
    for(int o=16;o;o>>=1) s+=__shfl_down_sync(0xffffffffu,s,o);
    if((t&31)==0) red[t>>5]=s;
    __syncthreads();
    if(t==0){
        float tot=0.f;
        #pragma unroll
        for(int i=0;i<8;i++) tot+=red[i];
        out[b]=g_flowcost[b]-g_dualedge[b]+tot;
    }
}

extern "C" void kernel_launch(void* const* d_in, const int* in_sizes, int n_in,
                              void* d_out, int out_size) {
    const float* feat  =(const float*)d_in[0];
    const float* emb   =(const float*)d_in[1];
    const float* dem   =(const float*)d_in[2];
    const float* adj   =(const float*)d_in[3];
    const float* nb    =(const float*)d_in[4];
    const float* enc_w0=(const float*)d_in[5];
    const float* enc_b0=(const float*)d_in[6];
    const float* enc_w1=(const float*)d_in[7];
    const float* enc_b1=(const float*)d_in[8];
    const float* agg_w =(const float*)d_in[9];
    const float* agg_b =(const float*)d_in[10];
    const float* att_w =(const float*)d_in[11];
    const float* att_b =(const float*)d_in[12];
    const float* att_v =(const float*)d_in[13];
    const float* gwu   =(const float*)d_in[14];
    const float* gbu   =(const float*)d_in[15];
    const float* gwr   =(const float*)d_in[16];
    const float* gbr   =(const float*)d_in[17];
    const float* gwc   =(const float*)d_in[18];
    const float* gbc   =(const float*)d_in[19];
    const float* dec_w0=(const float*)d_in[20];
    const float* dec_b0=(const float*)d_in[21];
    const float* dec_w1=(const float*)d_in[22];
    const float* dec_b1=(const float*)d_in[23];
    const float* dual_w0=(const float*)d_in[24];
    const float* dual_b0=(const float*)d_in[25];
    const float* dual_w1=(const float*)d_in[26];
    const float* dual_b1=(const float*)d_in[27];
    float* out=(float*)d_out;

    cudaFuncSetAttribute(k_node, cudaFuncAttributeMaxDynamicSharedMemorySize, SMB);
    cudaFuncSetAttribute(k_msg,  cudaFuncAttributeMaxDynamicSharedMemorySize, TS*64*4);

    k_comb<<<1,64>>>(dec_w0,dec_b0,dec_w1,dec_b1,dual_w0,dual_b0,dual_w1,dual_b1);
    k_enc<<<NGT/TN,128>>>(feat,emb,enc_w0,enc_b0,enc_w1,enc_b1);
    k_csr<<<3*NGT/8,256>>>(adj,nb);
    for(int layer=0;layer<2;layer++){
        k_msg<<<dim3(VV/RB,BB),256,TS*64*4>>>();
        k_node<<<NGT/TN,128,SMB>>>(agg_w,agg_b,att_w,att_b,att_v,
                                   gwu,gbu,gwr,gbr,gwc,gbc);
    }
    k_pred<<<NGT/8,256>>>();
    k_smax<<<NGT,64>>>();
    k_flow<<<BB,1024>>>(dem);
    k_dual<<<NGT/8,256>>>();
    k_final<<<BB,256>>>(dem,out);
}